// round 10
// baseline (speedup 1.0000x reference)
#include <cuda_runtime.h>
#include <math.h>

#define NF    64
#define NL    5
#define NMZI  2016
#define NCLS  12
#define TILE_R 64
#define TPB   256

#define CHALF 0.70710678118654752f
#define GAM   0.05f
#define GAM2  0.0025f

typedef unsigned int u32;
typedef unsigned short u16;

// strides (words)
#define AW    36          // K=64 plane row stride (72 bf16)
#define HW    68          // K=128 plane row stride (136 bf16)

// smem layout (bytes)
#define APL 9216                       // one K=64 plane (64 x 72 bf16)
#define OFF_A   0                      // 4 planes: frH frL fiH fiL = 36864
#define OFF_B   36864                  // B region 36864
#define OFF_W3  OFF_B                  // W3 overlay (3072)
#define OFF_H2  (OFF_B + 4096)         // h2 fp32 64x68 = 17408 (overlay)
#define OFF_PAR (OFF_B + 36864)        // 73728: 4 layers x 64 float4 = 4096
#define OFF_B1  (OFF_PAR + 4096)       // 77824: 128 f32
#define OFF_B2  (OFF_B1 + 512)         // 78336: 64 f32
#define SMEM_TOTAL 78592

// device global staging
// per layer compact block (u16 units): UrH@0 UiH@4608 UrL@9216 UiL@13824
__device__ __align__(16) u16 g_Bu[NL * 18432];
__device__ __align__(16) u16 g_Bw1[2 * 128 * 72];        // [hi][lo], stride 72
__device__ __align__(16) u16 g_Bw2[2 * 64 * 136];        // [hi][lo], stride 136

// ---------------- helpers ----------------
__device__ __forceinline__ u16 f2bf(float f) {
    u16 h; asm("cvt.rn.bf16.f32 %0, %1;" : "=h"(h) : "f"(f)); return h;
}
__device__ __forceinline__ u16 f2bf_hi(float f, float& fh) {
    u16 h; asm("cvt.rn.bf16.f32 %0, %1;" : "=h"(h) : "f"(f));
    fh = __uint_as_float(((u32)h) << 16); return h;
}
__device__ __forceinline__ u32 packbf(float lo, float hi) {
    u32 r; asm("cvt.rn.bf16x2.f32 %0, %1, %2;" : "=r"(r) : "f"(hi), "f"(lo)); return r;
}
__device__ __forceinline__ void mma_bf16(float* d, const u32* a, const u32* b) {
    asm volatile(
        "mma.sync.aligned.m16n8k16.row.col.f32.bf16.bf16.f32 "
        "{%0,%1,%2,%3},{%4,%5,%6,%7},{%8,%9},{%0,%1,%2,%3};"
        : "+f"(d[0]), "+f"(d[1]), "+f"(d[2]), "+f"(d[3])
        : "r"(a[0]), "r"(a[1]), "r"(a[2]), "r"(a[3]), "r"(b[0]), "r"(b[1]));
}
__device__ __forceinline__ void ldsm4(u32 addr, u32* r) {
    asm volatile("ldmatrix.sync.aligned.m8n8.x4.shared.b16 {%0,%1,%2,%3}, [%4];"
        : "=r"(r[0]), "=r"(r[1]), "=r"(r[2]), "=r"(r[3]) : "r"(addr));
}
__device__ __forceinline__ u32 smem_u32(const void* p) {
    u32 a;
    asm("{ .reg .u64 t; cvta.to.shared.u64 t, %1; cvt.u32.u64 %0, t; }" : "=r"(a) : "l"(p));
    return a;
}
__device__ __forceinline__ void cp16(u32 dst, const void* src) {
    asm volatile("cp.async.ca.shared.global [%0], [%1], 16;" :: "r"(dst), "l"(src));
}
__device__ __forceinline__ void cp_commit() {
    asm volatile("cp.async.commit_group;" ::: "memory");
}
__device__ __forceinline__ void cp_wait0() {
    asm volatile("cp.async.wait_group 0;" ::: "memory");
}

// Fused complex layer MMA: three accumulator sets, A fragments loaded once.
// Re1 += fr*Ur ; S2 += fi*Ui ; Im += fr*Ui + fi*Ur   (each 3-term bf16 split)
template <bool WITH_FI>
__device__ __forceinline__ void mma_layer(float a1[2][2][4], float a2[2][2][4],
                                          float aI[2][2][4],
                                          const u32* aFrH, const u32* aFrL,
                                          const u32* aFiH, const u32* aFiL,
                                          u32 bUrH, u32 bUrL, u32 bUiH, u32 bUiL) {
#pragma unroll
    for (int kk = 0; kk < 4; ++kk) {
        u32 frh[2][4], frl[2][4], fih[2][4], fil[2][4];
        ldsm4(aFrH[0] + kk * 32, frh[0]);
        ldsm4(aFrH[1] + kk * 32, frh[1]);
        ldsm4(aFrL[0] + kk * 32, frl[0]);
        ldsm4(aFrL[1] + kk * 32, frl[1]);
        if (WITH_FI) {
            ldsm4(aFiH[0] + kk * 32, fih[0]);
            ldsm4(aFiH[1] + kk * 32, fih[1]);
            ldsm4(aFiL[0] + kk * 32, fil[0]);
            ldsm4(aFiL[1] + kk * 32, fil[1]);
        }
        {   // Ur half
            u32 bh4[4], bl4[4];
            ldsm4(bUrH + kk * 32, bh4);
            ldsm4(bUrL + kk * 32, bl4);
#pragma unroll
            for (int mt = 0; mt < 2; ++mt)
#pragma unroll
                for (int nt = 0; nt < 2; ++nt) {
                    const u32* bh = bh4 + nt * 2;
                    const u32* bl = bl4 + nt * 2;
                    mma_bf16(a1[mt][nt], frh[mt], bh);
                    mma_bf16(a1[mt][nt], frh[mt], bl);
                    mma_bf16(a1[mt][nt], frl[mt], bh);
                    if (WITH_FI) {
                        mma_bf16(aI[mt][nt], fih[mt], bh);
                        mma_bf16(aI[mt][nt], fih[mt], bl);
                        mma_bf16(aI[mt][nt], fil[mt], bh);
                    }
                }
        }
        {   // Ui half
            u32 bh4[4], bl4[4];
            ldsm4(bUiH + kk * 32, bh4);
            ldsm4(bUiL + kk * 32, bl4);
#pragma unroll
            for (int mt = 0; mt < 2; ++mt)
#pragma unroll
                for (int nt = 0; nt < 2; ++nt) {
                    const u32* bh = bh4 + nt * 2;
                    const u32* bl = bl4 + nt * 2;
                    mma_bf16(aI[mt][nt], frh[mt], bh);
                    mma_bf16(aI[mt][nt], frh[mt], bl);
                    mma_bf16(aI[mt][nt], frl[mt], bh);
                    if (WITH_FI) {
                        mma_bf16(a2[mt][nt], fih[mt], bh);
                        mma_bf16(a2[mt][nt], fih[mt], bl);
                        mma_bf16(a2[mt][nt], fil[mt], bh);
                    }
                }
        }
    }
}

// N=128 K=64 block (GEMM1)
__device__ __forceinline__ void mma_blk128(float acc[2][4][4],
                                           const u32* aH, const u32* aL,
                                           const u32* bHp, const u32* bLp) {
#pragma unroll
    for (int kk = 0; kk < 4; ++kk) {
        u32 ah[2][4], al[2][4], b_h[2][4], b_l[2][4];
        ldsm4(aH[0] + kk * 32, ah[0]);
        ldsm4(aH[1] + kk * 32, ah[1]);
        ldsm4(aL[0] + kk * 32, al[0]);
        ldsm4(aL[1] + kk * 32, al[1]);
        ldsm4(bHp[0] + kk * 32, b_h[0]);
        ldsm4(bHp[1] + kk * 32, b_h[1]);
        ldsm4(bLp[0] + kk * 32, b_l[0]);
        ldsm4(bLp[1] + kk * 32, b_l[1]);
#pragma unroll
        for (int mt = 0; mt < 2; ++mt)
#pragma unroll
            for (int nt = 0; nt < 4; ++nt) {
                const u32* bh = &b_h[nt >> 1][(nt & 1) * 2];
                const u32* bl = &b_l[nt >> 1][(nt & 1) * 2];
                mma_bf16(acc[mt][nt], ah[mt], bh);
                mma_bf16(acc[mt][nt], ah[mt], bl);
                mma_bf16(acc[mt][nt], al[mt], bh);
            }
    }
}

// ---------------------------------------------------------------------------
// Unitary builder (blocks 0..4) + MLP weight prep (block 5).
// ---------------------------------------------------------------------------
__global__ void build_all(const float* __restrict__ mzi,
                          const float* __restrict__ ophase,
                          const float* __restrict__ W1,
                          const float* __restrict__ W2) {
    const int l = blockIdx.x;
    const int t = threadIdx.x;

    if (l == NL) {
        for (int idx = t; idx < 8192; idx += TPB) {
            int m = idx >> 6, j = idx & 63;
            float v = W1[idx];
            float fh; u16 h = f2bf_hi(v, fh); u16 lo = f2bf(v - fh);
            g_Bw1[m * 72 + j] = h;
            g_Bw1[128 * 72 + m * 72 + j] = lo;
        }
        for (int idx = t; idx < 8192; idx += TPB) {
            int n = idx >> 7, m = idx & 127;
            float v = W2[idx];
            float fh; u16 h = f2bf_hi(v, fh); u16 lo = f2bf(v - fh);
            g_Bw2[n * 136 + m] = h;
            g_Bw2[64 * 136 + n * 136 + m] = lo;
        }
        return;
    }

    extern __shared__ char sm[];
    float4* strig = (float4*)sm;
    float2* sU    = (float2*)(sm + 32272);
    float*  sco   = (float*)(sm + 67088);
    float*  ssi   = (float*)(sm + 67344);

    for (int k = t; k < NMZI; k += TPB) {
        float th = mzi[l * (2 * NMZI) + 2 * k];
        float ph = mzi[l * (2 * NMZI) + 2 * k + 1];
        float st, ct, sp, cp;
        sincosf(th, &st, &ct);
        sincosf(ph, &sp, &cp);
        strig[k] = make_float4(ct, st, CHALF * cp, CHALF * sp);
    }
    if (t == 0) strig[NMZI] = make_float4(0.f, 0.f, 0.f, 0.f);
    if (t < 64) {
        float s, c; sincosf(ophase[l * NF + t], &s, &c);
        sco[t] = c; ssi[t] = s;
    }
    for (int idx = t; idx < 68 * NF; idx += TPB) {
        int r = idx >> 6, c = idx & 63;
        sU[idx] = make_float2((r == c && r < 64) ? 1.f : 0.f, 0.f);
    }
    __syncthreads();

    if (t < 64) {
        int k = 0;
        for (int i = 0; i < 63; ++i) {
            float2 ui = sU[i * NF + t];
            float2 uj = sU[(i + 1) * NF + t];
            float4 tr = strig[k];
            for (int j = i + 1; j < 64; ++j) {
                float4 trn = strig[k + 1];
                float2 ujn = sU[(j + 1) * NF + t];
                float cepx = tr.z * uj.x - tr.w * uj.y;
                float cepy = tr.z * uj.y + tr.w * uj.x;
                float dxC = fmaf(CHALF, ui.x, -cepx);
                float dyC = fmaf(CHALF, ui.y, -cepy);
                float2 nj;
                nj.x = tr.x * dxC - tr.y * dyC;
                nj.y = tr.y * dxC + tr.x * dyC;
                sU[j * NF + t] = nj;
                ui.x = fmaf(CHALF, ui.x, cepx);
                ui.y = fmaf(CHALF, ui.y, cepy);
                uj = ujn; tr = trn; ++k;
            }
            sU[i * NF + t] = ui;
        }
    }
    __syncthreads();

    u16* gb = g_Bu + l * 18432;
    for (int idx = t; idx < NF * NF; idx += TPB) {
        int c = idx >> 6, j = idx & 63;
        float co = sco[c], si = ssi[c];
        float2 v = sU[c * NF + j];
        float ur = co * v.x - si * v.y;
        float um = co * v.y + si * v.x;
        float fh;
        u16 urh = f2bf_hi(ur, fh); u16 url = f2bf(ur - fh);
        u16 uih = f2bf_hi(um, fh); u16 uil = f2bf(um - fh);
        int w = c * 72 + j;
        gb[w]         = urh;
        gb[4608 + w]  = uih;
        gb[9216 + w]  = url;
        gb[13824 + w] = uil;
    }
}

// ---------------------------------------------------------------------------
// Main fused kernel.
// ---------------------------------------------------------------------------
__global__ __launch_bounds__(TPB, 2)
void ficonn_main(const float* __restrict__ x,
                 const float* __restrict__ beta_param,
                 const float* __restrict__ det0,
                 const float* __restrict__ b1,
                 const float* __restrict__ b2,
                 const float* __restrict__ W3, const float* __restrict__ b3,
                 float* __restrict__ out)
{
    extern __shared__ char smem[];
    const u32 sb = smem_u32(smem);
    const int t = threadIdx.x;
    const int wid = t >> 5;
    const int lane = t & 31;
    const int g = lane >> 2;
    const int q = lane & 3;
    const long base = (long)blockIdx.x * TILE_R;

    float4* sPar = (float4*)(smem + OFF_PAR);
    float*  sB1  = (float*)(smem + OFF_B1);
    float*  sB2  = (float*)(smem + OFF_B2);
    float*  sH2  = (float*)(smem + OFF_H2);

    const int m0  = (wid >> 2) * 32;
    const int nb  = (wid & 3) * 16;
    const int n0  = (wid & 3) * 32;

    const int mi    = lane >> 3;
    const int arow  = (mi & 1) * 8 + (lane & 7);
    const int aseg  = (mi >> 1) * 4;
    const int brow8 = (lane & 7);
    const int bnt   = (lane >> 4);
    const int bseg  = ((lane >> 3) & 1) * 4;

    // A plane frags: frH(0) frL(1) fiH(2) fiL(3)
    u32 aFrH[2], aFrL[2], aFiH[2], aFiL[2];
#pragma unroll
    for (int mt = 0; mt < 2; ++mt) {
        u32 off = 4 * ((m0 + mt * 16 + arow) * AW + aseg);
        aFrH[mt] = sb + OFF_A + 0 * APL + off;
        aFrL[mt] = sb + OFF_A + 1 * APL + off;
        aFiH[mt] = sb + OFF_A + 2 * APL + off;
        aFiL[mt] = sb + OFF_A + 3 * APL + off;
    }
    // B frags: UrH(0) UiH(1) UrL(2) UiL(3)
    const u32 bOff = 4 * ((nb + bnt * 8 + brow8) * AW + bseg);
    const u32 bUrH = sb + OFF_B + 0 * APL + bOff;
    const u32 bUiH = sb + OFF_B + 1 * APL + bOff;
    const u32 bUrL = sb + OFF_B + 2 * APL + bOff;
    const u32 bUiL = sb + OFF_B + 3 * APL + bOff;
    // W1 frags (N=128, stride AW)
    u32 w1H[2], w1L[2];
#pragma unroll
    for (int ntp = 0; ntp < 2; ++ntp) {
        u32 off = 4 * ((n0 + (ntp * 2 + bnt) * 8 + brow8) * AW + bseg);
        w1H[ntp] = sb + OFF_B + off;
        w1L[ntp] = sb + OFF_B + 18432 + off;
    }

    u32* pA = (u32*)(smem + OFF_A);

    // ---- init ----
    {
        const uint4* src = (const uint4*)g_Bu;
#pragma unroll
        for (int i = 0; i < 9; ++i)
            cp16(sb + OFF_B + 16 * (t + i * TPB), src + t + i * TPB);
        cp_commit();

        const float4* xv = (const float4*)(x + base * NF);
        for (int idx = t; idx < TILE_R * (NF / 4); idx += TPB) {
            int r = idx >> 4, c4 = (idx & 15) * 4;
            float4 v = xv[idx];
            u32 w01 = packbf(v.x, v.y);
            u32 w23 = packbf(v.z, v.w);
            float l0 = v.x - __uint_as_float(w01 << 16);
            float l1 = v.y - __uint_as_float(w01 & 0xFFFF0000u);
            float l2 = v.z - __uint_as_float(w23 << 16);
            float l3 = v.w - __uint_as_float(w23 & 0xFFFF0000u);
            int w = r * AW + (c4 >> 1);
            *(uint2*)(pA + w) = make_uint2(w01, w23);
            *(uint2*)(pA + APL / 4 + w) = make_uint2(packbf(l0, l1), packbf(l2, l3));
        }
        {
            int ll = t >> 6, c = t & 63;
            if (ll < NL - 1) {
                float bp = beta_param[ll * NF + c];
                float beta = 1.f / (1.f + expf(-bp));
                float sgam = sqrtf(fmaxf(1.f - beta, 0.f)) * GAM;
                sPar[t] = make_float4(sgam, 0.0008f * beta, det0[ll * NF + c], 0.f);
            }
        }
        if (t < 128) sB1[t] = b1[t];
        else if (t < 192) sB2[t - 128] = b2[t - 128];
    }

    // ================= photonic layers =================
    for (int l = 0; l < NL; ++l) {
        cp_wait0();
        __syncthreads();   // A + B(l) ready

        float a1[2][2][4], a2[2][2][4], aI[2][2][4];
#pragma unroll
        for (int mt = 0; mt < 2; ++mt)
#pragma unroll
            for (int nt = 0; nt < 2; ++nt)
#pragma unroll
                for (int e = 0; e < 4; ++e) {
                    a1[mt][nt][e] = 0.f; a2[mt][nt][e] = 0.f; aI[mt][nt][e] = 0.f;
                }

        if (l == 0)
            mma_layer<false>(a1, a2, aI, aFrH, aFrL, aFiH, aFiL, bUrH, bUrL, bUiH, bUiL);
        else
            mma_layer<true>(a1, a2, aI, aFrH, aFrL, aFiH, aFiL, bUrH, bUrL, bUiH, bUiL);
        __syncthreads();   // A + B reads done

        // stage next B (or W1) — overlaps epilogue
        {
            const uint4* src = (l < NL - 1)
                ? (const uint4*)(g_Bu + (l + 1) * 18432)
                : (const uint4*)g_Bw1;
#pragma unroll
            for (int i = 0; i < 9; ++i)
                cp16(sb + OFF_B + 16 * (t + i * TPB), src + t + i * TPB);
            cp_commit();
        }

        if (l < NL - 1) {
#pragma unroll
            for (int mt = 0; mt < 2; ++mt) {
#pragma unroll
                for (int nt = 0; nt < 2; ++nt) {
                    int c0 = nb + nt * 8 + q * 2;
                    float4 pr0 = sPar[l * 64 + c0];
                    float4 pr1 = sPar[l * 64 + c0 + 1];
#pragma unroll
                    for (int h = 0; h < 2; ++h) {
                        int row = m0 + mt * 16 + g + h * 8;
                        float ox[2], oy[2];
#pragma unroll
                        for (int e = 0; e < 2; ++e) {
                            float fx = a1[mt][nt][2 * h + e] - a2[mt][nt][2 * h + e];
                            float fy = aI[mt][nt][2 * h + e];
                            float4 pr = e ? pr1 : pr0;
                            float pw = fx * fx + fy * fy;
                            float det = fmaf(pr.y, pw, pr.z);
                            float s = pr.x * __fdividef(1.f, fmaf(det, det, GAM2));
                            ox[e] = s * fmaf(fy, det, fx * GAM);
                            oy[e] = s * fmaf(-fx, det, fy * GAM);
                        }
                        u32 frh = packbf(ox[0], ox[1]);
                        u32 frl = packbf(ox[0] - __uint_as_float(frh << 16),
                                         ox[1] - __uint_as_float(frh & 0xFFFF0000u));
                        u32 fih = packbf(oy[0], oy[1]);
                        u32 fil = packbf(oy[0] - __uint_as_float(fih << 16),
                                         oy[1] - __uint_as_float(fih & 0xFFFF0000u));
                        int w = row * AW + (c0 >> 1);
                        pA[w]               = frh;
                        pA[APL / 4 + w]     = frl;
                        pA[2 * APL / 4 + w] = fih;
                        pA[3 * APL / 4 + w] = fil;
                    }
                }
            }
        } else {
            // |field|^2 -> P planes (fr slots)
#pragma unroll
            for (int mt = 0; mt < 2; ++mt) {
#pragma unroll
                for (int nt = 0; nt < 2; ++nt) {
                    int c0 = nb + nt * 8 + q * 2;
#pragma unroll
                    for (int h = 0; h < 2; ++h) {
                        int row = m0 + mt * 16 + g + h * 8;
                        float fx0 = a1[mt][nt][2 * h]     - a2[mt][nt][2 * h];
                        float fx1 = a1[mt][nt][2 * h + 1] - a2[mt][nt][2 * h + 1];
                        float fy0 = aI[mt][nt][2 * h], fy1 = aI[mt][nt][2 * h + 1];
                        float pw0 = fx0 * fx0 + fy0 * fy0;
                        float pw1 = fx1 * fx1 + fy1 * fy1;
                        u32 ph = packbf(pw0, pw1);
                        u32 pl = packbf(pw0 - __uint_as_float(ph << 16),
                                        pw1 - __uint_as_float(ph & 0xFFFF0000u));
                        int w = row * AW + (c0 >> 1);
                        pA[w]           = ph;
                        pA[APL / 4 + w] = pl;
                    }
                }
            }
        }
    }
    cp_wait0();
    __syncthreads();   // P + W1 ready

    // ================= GEMM1: M=64 N=128 K=64 =================
    {
        float acc[2][4][4];
#pragma unroll
        for (int mt = 0; mt < 2; ++mt)
#pragma unroll
            for (int nt = 0; nt < 4; ++nt)
#pragma unroll
                for (int e = 0; e < 4; ++e) acc[mt][nt][e] = 0.f;

        mma_blk128(acc, aFrH, aFrL, w1H, w1L);
        __syncthreads();

        // stage W2 (34816 B = 2176 uint4)
        {
            const uint4* src = (const uint4*)g_Bw2;
            for (int i = t; i < 2176; i += TPB) cp16(sb + OFF_B + 16 * i, src + i);
            cp_commit();
        }
        // epilogue: relu+bias -> h1 planes (K=128 layout, stride HW)
#pragma unroll
        for (int mt = 0; mt < 2; ++mt) {
#pragma unroll
            for (int nt = 0; nt < 4; ++nt) {
                int col = n0 + nt * 8 + q * 2;
                float bb0 = sB1[col], bb1 = sB1[col + 1];
#pragma unroll
                for (int h = 0; h < 2; ++h) {
                    int row = m0 + mt * 16 + g + h * 8;
                    float v0 = fmaxf(acc[mt][nt][2 * h] + bb0, 0.f);
                    float v1 = fmaxf(acc[mt][nt][2 * h + 1] + bb1, 0.f);
                    u32 whi = packbf(v0, v1);
                    float l0 = v0 - __uint_as_float(whi << 16);
                    float l1 = v1 - __uint_as_float(whi & 0xFFFF0000u);
                    int w = row * HW + (col >> 1);
                    pA[w] = whi;
                    pA[17408 / 4 + w] = packbf(l0, l1);
                }
            }
        }
    }
    cp_wait0();
    __syncthreads();

    // ================= GEMM2: M=64 N=64 K=128 =================
    {
        const int mb  = (wid >> 1) * 16;
        const int nb2 = (wid & 1) * 32;

        u32 aA2h = sb + OFF_A + 4 * ((mb + arow) * HW + aseg);
        u32 aA2l = aA2h + 17408;
        u32 b2H[2], b2L[2];
#pragma unroll
        for (int ntp = 0; ntp < 2; ++ntp) {
            u32 off = 4 * ((nb2 + (ntp * 2 + bnt) * 8 + brow8) * HW + bseg);
            b2H[ntp] = sb + OFF_B + off;
            b2L[ntp] = sb + OFF_B + 17408 + off;
        }

        float acc[4][4];
#pragma unroll
        for (int nt = 0; nt < 4; ++nt)
#pragma unroll
            for (int e = 0; e < 4; ++e) acc[nt][e] = 0.f;

#pragma unroll
        for (int kk = 0; kk < 8; ++kk) {
            u32 ah[4], al[4], b_h[2][4], b_l[2][4];
            ldsm4(aA2h + kk * 32, ah);
            ldsm4(aA2l + kk * 32, al);
            ldsm4(b2H[0] + kk * 32, b_h[0]);
            ldsm4(b2H[1] + kk * 32, b_h[1]);
            ldsm4(b2L[0] + kk * 32, b_l[0]);
            ldsm4(b2L[1] + kk * 32, b_l[1]);
#pragma unroll
            for (int nt = 0; nt < 4; ++nt) {
                const u32* bh = &b_h[nt >> 1][(nt & 1) * 2];
                const u32* bl = &b_l[nt >> 1][(nt & 1) * 2];
                mma_bf16(acc[nt], ah, bh);
                mma_bf16(acc[nt], ah, bl);
                mma_bf16(acc[nt], al, bh);
            }
        }
        __syncthreads();   // h1/W2 reads done

        {
            float* sW3 = (float*)(smem + OFF_W3);
            for (int i = t; i < NCLS * 64; i += TPB) sW3[i] = W3[i];
        }
#pragma unroll
        for (int nt = 0; nt < 4; ++nt) {
            int col = nb2 + nt * 8 + q * 2;
            float bb0 = sB2[col], bb1 = sB2[col + 1];
#pragma unroll
            for (int h = 0; h < 2; ++h) {
                int row = mb + g + h * 8;
                sH2[row * 68 + col]     = fmaxf(acc[nt][2 * h] + bb0, 0.f);
                sH2[row * 68 + col + 1] = fmaxf(acc[nt][2 * h + 1] + bb1, 0.f);
            }
        }
    }
    __syncthreads();

    // ================= GEMM3 (scalar) =================
    {
        const float* sW3 = (const float*)(smem + OFF_W3);
        const int rr = t >> 2;
        const int ch = (t & 3) * 3;
        float acc[3] = {0.f, 0.f, 0.f};
#pragma unroll 4
        for (int j = 0; j < 64; ++j) {
            float h = sH2[rr * 68 + j];
#pragma unroll
            for (int c = 0; c < 3; ++c)
                acc[c] = fmaf(h, sW3[(ch + c) * 64 + j], acc[c]);
        }
#pragma unroll
        for (int c = 0; c < 3; ++c)
            out[(base + rr) * NCLS + ch + c] = acc[c] + b3[ch + c];
    }
}

// ---------------------------------------------------------------------------
extern "C" void kernel_launch(void* const* d_in, const int* in_sizes, int n_in,
                              void* d_out, int out_size) {
    const float* x     = (const float*)d_in[0];
    const float* mzi   = (const float*)d_in[1];
    const float* oph   = (const float*)d_in[2];
    const float* betap = (const float*)d_in[3];
    const float* det0  = (const float*)d_in[4];
    const float* W1    = (const float*)d_in[5];
    const float* b1    = (const float*)d_in[6];
    const float* W2    = (const float*)d_in[7];
    const float* b2    = (const float*)d_in[8];
    const float* W3    = (const float*)d_in[9];
    const float* b3    = (const float*)d_in[10];
    float* out = (float*)d_out;

    const int rows = in_sizes[0] / NF;
    const int grid = rows / TILE_R;

    cudaFuncSetAttribute(build_all, cudaFuncAttributeMaxDynamicSharedMemorySize, 67712);
    cudaFuncSetAttribute(ficonn_main, cudaFuncAttributeMaxDynamicSharedMemorySize, SMEM_TOTAL);

    build_all<<<NL + 1, TPB, 67712>>>(mzi, oph, W1, W2);
    ficonn_main<<<grid, TPB, SMEM_TOTAL>>>(x, betap, det0, b1, b2, W3, b3, out);
}

// round 11
// speedup vs baseline: 1.0815x; 1.0815x over previous
#include <cuda_runtime.h>
#include <math.h>

#define NF    64
#define NL    5
#define NMZI  2016
#define NCLS  12
#define TILE_R 64
#define TPB   256

#define CHALF 0.70710678118654752f
#define GAM   0.05f
#define GAM2  0.0025f

typedef unsigned int u32;
typedef unsigned short u16;

// strides (words)
#define AW    36          // K=64 plane row stride (72 bf16)
#define HW    68          // K=128 plane row stride (136 bf16)

// smem layout (bytes)
#define APL 9216                       // one K=64 plane (64 x 72 bf16)
#define OFF_A   0                      // 4 planes: frH frL fiH fiL = 36864
#define OFF_B   36864                  // B region 36864
#define OFF_W3  OFF_B                  // W3 overlay (3072)
#define OFF_H2  (OFF_B + 4096)         // h2 fp32 64x68 = 17408 (overlay)
#define OFF_PAR (OFF_B + 36864)        // 73728: 4 layers x 64 float4 = 4096
#define OFF_B1  (OFF_PAR + 4096)       // 77824
#define OFF_B2  (OFF_B1 + 512)         // 78336
#define SMEM_TOTAL 78592

// device global staging: per layer (u16 units): UrH@0 UiH@4608 UrL@9216 UiL@13824
__device__ __align__(16) u16 g_Bu[NL * 18432];
__device__ __align__(16) u16 g_Bw1[2 * 128 * 72];        // [hi][lo], stride 72
__device__ __align__(16) u16 g_Bw2[2 * 64 * 136];        // [hi][lo], stride 136

// ---------------- helpers ----------------
__device__ __forceinline__ u16 f2bf(float f) {
    u16 h; asm("cvt.rn.bf16.f32 %0, %1;" : "=h"(h) : "f"(f)); return h;
}
__device__ __forceinline__ u16 f2bf_hi(float f, float& fh) {
    u16 h; asm("cvt.rn.bf16.f32 %0, %1;" : "=h"(h) : "f"(f));
    fh = __uint_as_float(((u32)h) << 16); return h;
}
__device__ __forceinline__ u32 packbf(float lo, float hi) {
    u32 r; asm("cvt.rn.bf16x2.f32 %0, %1, %2;" : "=r"(r) : "f"(hi), "f"(lo)); return r;
}
__device__ __forceinline__ void mma_bf16(float* d, const u32* a, const u32* b) {
    asm volatile(
        "mma.sync.aligned.m16n8k16.row.col.f32.bf16.bf16.f32 "
        "{%0,%1,%2,%3},{%4,%5,%6,%7},{%8,%9},{%0,%1,%2,%3};"
        : "+f"(d[0]), "+f"(d[1]), "+f"(d[2]), "+f"(d[3])
        : "r"(a[0]), "r"(a[1]), "r"(a[2]), "r"(a[3]), "r"(b[0]), "r"(b[1]));
}
__device__ __forceinline__ void ldsm4(u32 addr, u32* r) {
    asm volatile("ldmatrix.sync.aligned.m8n8.x4.shared.b16 {%0,%1,%2,%3}, [%4];"
        : "=r"(r[0]), "=r"(r[1]), "=r"(r[2]), "=r"(r[3]) : "r"(addr));
}
__device__ __forceinline__ u32 smem_u32(const void* p) {
    u32 a;
    asm("{ .reg .u64 t; cvta.to.shared.u64 t, %1; cvt.u32.u64 %0, t; }" : "=r"(a) : "l"(p));
    return a;
}
__device__ __forceinline__ void cp16(u32 dst, const void* src) {
    asm volatile("cp.async.ca.shared.global [%0], [%1], 16;" :: "r"(dst), "l"(src));
}
__device__ __forceinline__ void cp_commit() {
    asm volatile("cp.async.commit_group;" ::: "memory");
}
__device__ __forceinline__ void cp_wait0() {
    asm volatile("cp.async.wait_group 0;" ::: "memory");
}

// K=64 product block, TERM-OUTER ordering (consecutive MMAs hit distinct accs).
// acc += (Ah+Al)*Bh + Ah*Bl
__device__ __forceinline__ void mma_blk64(float acc[2][2][4],
                                          const u32* aH, const u32* aL,
                                          u32 bH, u32 bL) {
#pragma unroll
    for (int kk = 0; kk < 4; ++kk) {
        u32 ah[2][4], al[2][4], bh4[4], bl4[4];
        ldsm4(aH[0] + kk * 32, ah[0]);
        ldsm4(aH[1] + kk * 32, ah[1]);
        ldsm4(aL[0] + kk * 32, al[0]);
        ldsm4(aL[1] + kk * 32, al[1]);
        ldsm4(bH + kk * 32, bh4);
        ldsm4(bL + kk * 32, bl4);
        // term 1: Ah*Bh
#pragma unroll
        for (int mt = 0; mt < 2; ++mt)
#pragma unroll
            for (int nt = 0; nt < 2; ++nt)
                mma_bf16(acc[mt][nt], ah[mt], bh4 + nt * 2);
        // term 2: Ah*Bl
#pragma unroll
        for (int mt = 0; mt < 2; ++mt)
#pragma unroll
            for (int nt = 0; nt < 2; ++nt)
                mma_bf16(acc[mt][nt], ah[mt], bl4 + nt * 2);
        // term 3: Al*Bh
#pragma unroll
        for (int mt = 0; mt < 2; ++mt)
#pragma unroll
            for (int nt = 0; nt < 2; ++nt)
                mma_bf16(acc[mt][nt], al[mt], bh4 + nt * 2);
    }
}

// N=128 K=64 block (GEMM1), term-outer ordering
__device__ __forceinline__ void mma_blk128(float acc[2][4][4],
                                           const u32* aH, const u32* aL,
                                           const u32* bHp, const u32* bLp) {
#pragma unroll
    for (int kk = 0; kk < 4; ++kk) {
        u32 ah[2][4], al[2][4], b_h[2][4], b_l[2][4];
        ldsm4(aH[0] + kk * 32, ah[0]);
        ldsm4(aH[1] + kk * 32, ah[1]);
        ldsm4(aL[0] + kk * 32, al[0]);
        ldsm4(aL[1] + kk * 32, al[1]);
        ldsm4(bHp[0] + kk * 32, b_h[0]);
        ldsm4(bHp[1] + kk * 32, b_h[1]);
        ldsm4(bLp[0] + kk * 32, b_l[0]);
        ldsm4(bLp[1] + kk * 32, b_l[1]);
#pragma unroll
        for (int mt = 0; mt < 2; ++mt)
#pragma unroll
            for (int nt = 0; nt < 4; ++nt)
                mma_bf16(acc[mt][nt], ah[mt], &b_h[nt >> 1][(nt & 1) * 2]);
#pragma unroll
        for (int mt = 0; mt < 2; ++mt)
#pragma unroll
            for (int nt = 0; nt < 4; ++nt)
                mma_bf16(acc[mt][nt], ah[mt], &b_l[nt >> 1][(nt & 1) * 2]);
#pragma unroll
        for (int mt = 0; mt < 2; ++mt)
#pragma unroll
            for (int nt = 0; nt < 4; ++nt)
                mma_bf16(acc[mt][nt], al[mt], &b_h[nt >> 1][(nt & 1) * 2]);
    }
}

// ---------------------------------------------------------------------------
// Unitary builder (blocks 0..4) + MLP weight prep (block 5).
// ---------------------------------------------------------------------------
__global__ void build_all(const float* __restrict__ mzi,
                          const float* __restrict__ ophase,
                          const float* __restrict__ W1,
                          const float* __restrict__ W2) {
    const int l = blockIdx.x;
    const int t = threadIdx.x;

    if (l == NL) {
        for (int idx = t; idx < 8192; idx += TPB) {
            int m = idx >> 6, j = idx & 63;
            float v = W1[idx];
            float fh; u16 h = f2bf_hi(v, fh); u16 lo = f2bf(v - fh);
            g_Bw1[m * 72 + j] = h;
            g_Bw1[128 * 72 + m * 72 + j] = lo;
        }
        for (int idx = t; idx < 8192; idx += TPB) {
            int n = idx >> 7, m = idx & 127;
            float v = W2[idx];
            float fh; u16 h = f2bf_hi(v, fh); u16 lo = f2bf(v - fh);
            g_Bw2[n * 136 + m] = h;
            g_Bw2[64 * 136 + n * 136 + m] = lo;
        }
        return;
    }

    extern __shared__ char sm[];
    float4* strig = (float4*)sm;
    float2* sU    = (float2*)(sm + 32272);
    float*  sco   = (float*)(sm + 67088);
    float*  ssi   = (float*)(sm + 67344);

    for (int k = t; k < NMZI; k += TPB) {
        float th = mzi[l * (2 * NMZI) + 2 * k];
        float ph = mzi[l * (2 * NMZI) + 2 * k + 1];
        float st, ct, sp, cp;
        sincosf(th, &st, &ct);
        sincosf(ph, &sp, &cp);
        strig[k] = make_float4(ct, st, CHALF * cp, CHALF * sp);
    }
    if (t == 0) strig[NMZI] = make_float4(0.f, 0.f, 0.f, 0.f);
    if (t < 64) {
        float s, c; sincosf(ophase[l * NF + t], &s, &c);
        sco[t] = c; ssi[t] = s;
    }
    for (int idx = t; idx < 68 * NF; idx += TPB) {
        int r = idx >> 6, c = idx & 63;
        sU[idx] = make_float2((r == c && r < 64) ? 1.f : 0.f, 0.f);
    }
    __syncthreads();

    if (t < 64) {
        int k = 0;
        for (int i = 0; i < 63; ++i) {
            float2 ui = sU[i * NF + t];
            float2 uj = sU[(i + 1) * NF + t];
            float4 tr = strig[k];
            for (int j = i + 1; j < 64; ++j) {
                float4 trn = strig[k + 1];
                float2 ujn = sU[(j + 1) * NF + t];
                float cepx = tr.z * uj.x - tr.w * uj.y;
                float cepy = tr.z * uj.y + tr.w * uj.x;
                float dxC = fmaf(CHALF, ui.x, -cepx);
                float dyC = fmaf(CHALF, ui.y, -cepy);
                float2 nj;
                nj.x = tr.x * dxC - tr.y * dyC;
                nj.y = tr.y * dxC + tr.x * dyC;
                sU[j * NF + t] = nj;
                ui.x = fmaf(CHALF, ui.x, cepx);
                ui.y = fmaf(CHALF, ui.y, cepy);
                uj = ujn; tr = trn; ++k;
            }
            sU[i * NF + t] = ui;
        }
    }
    __syncthreads();

    u16* gb = g_Bu + l * 18432;
    for (int idx = t; idx < NF * NF; idx += TPB) {
        int c = idx >> 6, j = idx & 63;
        float co = sco[c], si = ssi[c];
        float2 v = sU[c * NF + j];
        float ur = co * v.x - si * v.y;
        float um = co * v.y + si * v.x;
        float fh;
        u16 urh = f2bf_hi(ur, fh); u16 url = f2bf(ur - fh);
        u16 uih = f2bf_hi(um, fh); u16 uil = f2bf(um - fh);
        int w = c * 72 + j;
        gb[w]         = urh;
        gb[4608 + w]  = uih;
        gb[9216 + w]  = url;
        gb[13824 + w] = uil;
    }
}

// ---------------------------------------------------------------------------
// Main fused kernel.
// ---------------------------------------------------------------------------
__global__ __launch_bounds__(TPB, 2)
void ficonn_main(const float* __restrict__ x,
                 const float* __restrict__ beta_param,
                 const float* __restrict__ det0,
                 const float* __restrict__ b1,
                 const float* __restrict__ b2,
                 const float* __restrict__ W3, const float* __restrict__ b3,
                 float* __restrict__ out)
{
    extern __shared__ char smem[];
    const u32 sb = smem_u32(smem);
    const int t = threadIdx.x;
    const int wid = t >> 5;
    const int lane = t & 31;
    const int g = lane >> 2;
    const int q = lane & 3;
    const long base = (long)blockIdx.x * TILE_R;

    float4* sPar = (float4*)(smem + OFF_PAR);
    float*  sB1  = (float*)(smem + OFF_B1);
    float*  sB2  = (float*)(smem + OFF_B2);
    float*  sH2  = (float*)(smem + OFF_H2);

    const int m0  = (wid >> 2) * 32;
    const int nb  = (wid & 3) * 16;
    const int n0  = (wid & 3) * 32;

    const int mi    = lane >> 3;
    const int arow  = (mi & 1) * 8 + (lane & 7);
    const int aseg  = (mi >> 1) * 4;
    const int brow8 = (lane & 7);
    const int bnt   = (lane >> 4);
    const int bseg  = ((lane >> 3) & 1) * 4;

    // A plane frags: frH(0) frL(1) fiH(2) fiL(3)
    u32 aFrH[2], aFrL[2], aFiH[2], aFiL[2];
#pragma unroll
    for (int mt = 0; mt < 2; ++mt) {
        u32 off = 4 * ((m0 + mt * 16 + arow) * AW + aseg);
        aFrH[mt] = sb + OFF_A + 0 * APL + off;
        aFrL[mt] = sb + OFF_A + 1 * APL + off;
        aFiH[mt] = sb + OFF_A + 2 * APL + off;
        aFiL[mt] = sb + OFF_A + 3 * APL + off;
    }
    // B frags: UrH(0) UiH(1) UrL(2) UiL(3)
    const u32 bOff = 4 * ((nb + bnt * 8 + brow8) * AW + bseg);
    const u32 bUrH = sb + OFF_B + 0 * APL + bOff;
    const u32 bUiH = sb + OFF_B + 1 * APL + bOff;
    const u32 bUrL = sb + OFF_B + 2 * APL + bOff;
    const u32 bUiL = sb + OFF_B + 3 * APL + bOff;
    // W1 frags (N=128, stride AW)
    u32 w1H[2], w1L[2];
#pragma unroll
    for (int ntp = 0; ntp < 2; ++ntp) {
        u32 off = 4 * ((n0 + (ntp * 2 + bnt) * 8 + brow8) * AW + bseg);
        w1H[ntp] = sb + OFF_B + off;
        w1L[ntp] = sb + OFF_B + 18432 + off;
    }

    u32* pA = (u32*)(smem + OFF_A);

    // ---- init ----
    {
        const uint4* src = (const uint4*)g_Bu;
#pragma unroll
        for (int i = 0; i < 9; ++i)
            cp16(sb + OFF_B + 16 * (t + i * TPB), src + t + i * TPB);
        cp_commit();

        const float4* xv = (const float4*)(x + base * NF);
        for (int idx = t; idx < TILE_R * (NF / 4); idx += TPB) {
            int r = idx >> 4, c4 = (idx & 15) * 4;
            float4 v = xv[idx];
            u32 w01 = packbf(v.x, v.y);
            u32 w23 = packbf(v.z, v.w);
            float l0 = v.x - __uint_as_float(w01 << 16);
            float l1 = v.y - __uint_as_float(w01 & 0xFFFF0000u);
            float l2 = v.z - __uint_as_float(w23 << 16);
            float l3 = v.w - __uint_as_float(w23 & 0xFFFF0000u);
            int w = r * AW + (c4 >> 1);
            *(uint2*)(pA + w) = make_uint2(w01, w23);
            *(uint2*)(pA + APL / 4 + w) = make_uint2(packbf(l0, l1), packbf(l2, l3));
        }
        {
            int ll = t >> 6, c = t & 63;
            if (ll < NL - 1) {
                float bp = beta_param[ll * NF + c];
                float beta = 1.f / (1.f + expf(-bp));
                float sgam = sqrtf(fmaxf(1.f - beta, 0.f)) * GAM;
                sPar[t] = make_float4(sgam, 0.0008f * beta, det0[ll * NF + c], 0.f);
            }
        }
        if (t < 128) sB1[t] = b1[t];
        else if (t < 192) sB2[t - 128] = b2[t - 128];
    }

    // ================= photonic layers =================
    for (int l = 0; l < NL; ++l) {
        cp_wait0();
        __syncthreads();   // A + B(l) ready

        float a1[2][2][4], a2[2][2][4], aI[2][2][4];
#pragma unroll
        for (int mt = 0; mt < 2; ++mt)
#pragma unroll
            for (int nt = 0; nt < 2; ++nt)
#pragma unroll
                for (int e = 0; e < 4; ++e) {
                    a1[mt][nt][e] = 0.f; a2[mt][nt][e] = 0.f; aI[mt][nt][e] = 0.f;
                }

        mma_blk64(a1, aFrH, aFrL, bUrH, bUrL);     // fr*Ur
        mma_blk64(aI, aFrH, aFrL, bUiH, bUiL);     // fr*Ui
        if (l > 0) {
            mma_blk64(a2, aFiH, aFiL, bUiH, bUiL); // fi*Ui (subtract later)
            mma_blk64(aI, aFiH, aFiL, bUrH, bUrL); // fi*Ur
        }
        __syncthreads();   // A + B reads done

        // stage next B (or W1) — overlaps epilogue
        {
            const uint4* src = (l < NL - 1)
                ? (const uint4*)(g_Bu + (l + 1) * 18432)
                : (const uint4*)g_Bw1;
#pragma unroll
            for (int i = 0; i < 9; ++i)
                cp16(sb + OFF_B + 16 * (t + i * TPB), src + t + i * TPB);
            cp_commit();
        }

        if (l < NL - 1) {
#pragma unroll
            for (int mt = 0; mt < 2; ++mt) {
#pragma unroll
                for (int nt = 0; nt < 2; ++nt) {
                    int c0 = nb + nt * 8 + q * 2;
                    float4 pr0 = sPar[l * 64 + c0];
                    float4 pr1 = sPar[l * 64 + c0 + 1];
#pragma unroll
                    for (int h = 0; h < 2; ++h) {
                        int row = m0 + mt * 16 + g + h * 8;
                        float ox[2], oy[2];
#pragma unroll
                        for (int e = 0; e < 2; ++e) {
                            float fx = a1[mt][nt][2 * h + e] - a2[mt][nt][2 * h + e];
                            float fy = aI[mt][nt][2 * h + e];
                            float4 pr = e ? pr1 : pr0;
                            float pw = fx * fx + fy * fy;
                            float det = fmaf(pr.y, pw, pr.z);
                            float s = pr.x * __fdividef(1.f, fmaf(det, det, GAM2));
                            ox[e] = s * fmaf(fy, det, fx * GAM);
                            oy[e] = s * fmaf(-fx, det, fy * GAM);
                        }
                        u32 frh = packbf(ox[0], ox[1]);
                        u32 frl = packbf(ox[0] - __uint_as_float(frh << 16),
                                         ox[1] - __uint_as_float(frh & 0xFFFF0000u));
                        u32 fih = packbf(oy[0], oy[1]);
                        u32 fil = packbf(oy[0] - __uint_as_float(fih << 16),
                                         oy[1] - __uint_as_float(fih & 0xFFFF0000u));
                        int w = row * AW + (c0 >> 1);
                        pA[w]               = frh;
                        pA[APL / 4 + w]     = frl;
                        pA[2 * APL / 4 + w] = fih;
                        pA[3 * APL / 4 + w] = fil;
                    }
                }
            }
        } else {
            // |field|^2 -> P planes (fr slots)
#pragma unroll
            for (int mt = 0; mt < 2; ++mt) {
#pragma unroll
                for (int nt = 0; nt < 2; ++nt) {
                    int c0 = nb + nt * 8 + q * 2;
#pragma unroll
                    for (int h = 0; h < 2; ++h) {
                        int row = m0 + mt * 16 + g + h * 8;
                        float fx0 = a1[mt][nt][2 * h]     - a2[mt][nt][2 * h];
                        float fx1 = a1[mt][nt][2 * h + 1] - a2[mt][nt][2 * h + 1];
                        float fy0 = aI[mt][nt][2 * h], fy1 = aI[mt][nt][2 * h + 1];
                        float pw0 = fx0 * fx0 + fy0 * fy0;
                        float pw1 = fx1 * fx1 + fy1 * fy1;
                        u32 ph = packbf(pw0, pw1);
                        u32 pl = packbf(pw0 - __uint_as_float(ph << 16),
                                        pw1 - __uint_as_float(ph & 0xFFFF0000u));
                        int w = row * AW + (c0 >> 1);
                        pA[w]           = ph;
                        pA[APL / 4 + w] = pl;
                    }
                }
            }
        }
    }
    cp_wait0();
    __syncthreads();   // P + W1 ready

    // ================= GEMM1: M=64 N=128 K=64 =================
    {
        float acc[2][4][4];
#pragma unroll
        for (int mt = 0; mt < 2; ++mt)
#pragma unroll
            for (int nt = 0; nt < 4; ++nt)
#pragma unroll
                for (int e = 0; e < 4; ++e) acc[mt][nt][e] = 0.f;

        mma_blk128(acc, aFrH, aFrL, w1H, w1L);
        __syncthreads();

        // stage W2 (34816 B = 2176 uint4)
        {
            const uint4* src = (const uint4*)g_Bw2;
            for (int i = t; i < 2176; i += TPB) cp16(sb + OFF_B + 16 * i, src + i);
            cp_commit();
        }
        // epilogue: relu+bias -> h1 planes (K=128 layout, stride HW)
#pragma unroll
        for (int mt = 0; mt < 2; ++mt) {
#pragma unroll
            for (int nt = 0; nt < 4; ++nt) {
                int col = n0 + nt * 8 + q * 2;
                float bb0 = sB1[col], bb1 = sB1[col + 1];
#pragma unroll
                for (int h = 0; h < 2; ++h) {
                    int row = m0 + mt * 16 + g + h * 8;
                    float v0 = fmaxf(acc[mt][nt][2 * h] + bb0, 0.f);
                    float v1 = fmaxf(acc[mt][nt][2 * h + 1] + bb1, 0.f);
                    u32 whi = packbf(v0, v1);
                    float l0 = v0 - __uint_as_float(whi << 16);
                    float l1 = v1 - __uint_as_float(whi & 0xFFFF0000u);
                    int w = row * HW + (col >> 1);
                    pA[w] = whi;
                    pA[17408 / 4 + w] = packbf(l0, l1);
                }
            }
        }
    }
    cp_wait0();
    __syncthreads();

    // ================= GEMM2: M=64 N=64 K=128 =================
    {
        const int mb  = (wid >> 1) * 16;
        const int nb2 = (wid & 1) * 32;

        u32 aA2h = sb + OFF_A + 4 * ((mb + arow) * HW + aseg);
        u32 aA2l = aA2h + 17408;
        u32 b2H[2], b2L[2];
#pragma unroll
        for (int ntp = 0; ntp < 2; ++ntp) {
            u32 off = 4 * ((nb2 + (ntp * 2 + bnt) * 8 + brow8) * HW + bseg);
            b2H[ntp] = sb + OFF_B + off;
            b2L[ntp] = sb + OFF_B + 17408 + off;
        }

        float acc[4][4];
#pragma unroll
        for (int nt = 0; nt < 4; ++nt)
#pragma unroll
            for (int e = 0; e < 4; ++e) acc[nt][e] = 0.f;

#pragma unroll
        for (int kk = 0; kk < 8; ++kk) {
            u32 ah[4], al[4], b_h[2][4], b_l[2][4];
            ldsm4(aA2h + kk * 32, ah);
            ldsm4(aA2l + kk * 32, al);
            ldsm4(b2H[0] + kk * 32, b_h[0]);
            ldsm4(b2H[1] + kk * 32, b_h[1]);
            ldsm4(b2L[0] + kk * 32, b_l[0]);
            ldsm4(b2L[1] + kk * 32, b_l[1]);
            // term-outer ordering
#pragma unroll
            for (int nt = 0; nt < 4; ++nt)
                mma_bf16(acc[nt], ah, &b_h[nt >> 1][(nt & 1) * 2]);
#pragma unroll
            for (int nt = 0; nt < 4; ++nt)
                mma_bf16(acc[nt], ah, &b_l[nt >> 1][(nt & 1) * 2]);
#pragma unroll
            for (int nt = 0; nt < 4; ++nt)
                mma_bf16(acc[nt], al, &b_h[nt >> 1][(nt & 1) * 2]);
        }
        __syncthreads();   // h1/W2 reads done

        {
            float* sW3 = (float*)(smem + OFF_W3);
            for (int i = t; i < NCLS * 64; i += TPB) sW3[i] = W3[i];
        }
#pragma unroll
        for (int nt = 0; nt < 4; ++nt) {
            int col = nb2 + nt * 8 + q * 2;
            float bb0 = sB2[col], bb1 = sB2[col + 1];
#pragma unroll
            for (int h = 0; h < 2; ++h) {
                int row = mb + g + h * 8;
                sH2[row * 68 + col]     = fmaxf(acc[nt][2 * h] + bb0, 0.f);
                sH2[row * 68 + col + 1] = fmaxf(acc[nt][2 * h + 1] + bb1, 0.f);
            }
        }
    }
    __syncthreads();

    // ================= GEMM3 (scalar) =================
    {
        const float* sW3 = (const float*)(smem + OFF_W3);
        const int rr = t >> 2;
        const int ch = (t & 3) * 3;
        float acc[3] = {0.f, 0.f, 0.f};
#pragma unroll 4
        for (int j = 0; j < 64; ++j) {
            float h = sH2[rr * 68 + j];
#pragma unroll
            for (int c = 0; c < 3; ++c)
                acc[c] = fmaf(h, sW3[(ch + c) * 64 + j], acc[c]);
        }
#pragma unroll
        for (int c = 0; c < 3; ++c)
            out[(base + rr) * NCLS + ch + c] = acc[c] + b3[ch + c];
    }
}

// ---------------------------------------------------------------------------
extern "C" void kernel_launch(void* const* d_in, const int* in_sizes, int n_in,
                              void* d_out, int out_size) {
    const float* x     = (const float*)d_in[0];
    const float* mzi   = (const float*)d_in[1];
    const float* oph   = (const float*)d_in[2];
    const float* betap = (const float*)d_in[3];
    const float* det0  = (const float*)d_in[4];
    const float* W1    = (const float*)d_in[5];
    const float* b1    = (const float*)d_in[6];
    const float* W2    = (const float*)d_in[7];
    const float* b2    = (const float*)d_in[8];
    const float* W3    = (const float*)d_in[9];
    const float* b3    = (const float*)d_in[10];
    float* out = (float*)d_out;

    const int rows = in_sizes[0] / NF;
    const int grid = rows / TILE_R;

    cudaFuncSetAttribute(build_all, cudaFuncAttributeMaxDynamicSharedMemorySize, 67712);
    cudaFuncSetAttribute(ficonn_main, cudaFuncAttributeMaxDynamicSharedMemorySize, SMEM_TOTAL);

    build_all<<<NL + 1, TPB, 67712>>>(mzi, oph, W1, W2);
    ficonn_main<<<grid, TPB, SMEM_TOTAL>>>(x, betap, det0, b1, b2, W3, b3, out);
}

// round 12
// speedup vs baseline: 1.0918x; 1.0095x over previous
#include <cuda_runtime.h>
#include <math.h>

#define NF    64
#define NL    5
#define NMZI  2016
#define NCLS  12
#define TILE_R 64
#define TPB   256

#define CHALF 0.70710678118654752f
#define GAM   0.05f
#define GAM2  0.0025f

typedef unsigned int u32;
typedef unsigned short u16;

// strides (words)
#define AW    36          // K=64 plane row stride (72 bf16)
#define HW    68          // K=128 plane row stride (136 bf16)

// smem layout (bytes)
#define APL 9216                       // one K=64 plane (64 x 72 bf16)
#define OFF_A   0                      // 4 planes: frH frL fiH fiL = 36864
#define OFF_B   36864                  // B region 36864
#define OFF_W3  OFF_B                  // W3 overlay (3072)
#define OFF_H2  (OFF_B + 4096)         // h2 fp32 64x68 = 17408 (overlay)
#define OFF_PAR (OFF_B + 36864)        // 73728: 4 layers x 64 float4 = 4096
#define OFF_B1  (OFF_PAR + 4096)       // 77824
#define OFF_B2  (OFF_B1 + 512)         // 78336
#define SMEM_TOTAL 78592

// device global staging: per layer (u16 units): UrH@0 UiH@4608 UrL@9216 UiL@13824
__device__ __align__(16) u16 g_Bu[NL * 18432];
__device__ __align__(16) u16 g_Bw1[2 * 128 * 72];        // [hi][lo], stride 72
__device__ __align__(16) u16 g_Bw2[2 * 64 * 136];        // [hi][lo], stride 136

// ---------------- helpers ----------------
__device__ __forceinline__ u16 f2bf(float f) {
    u16 h; asm("cvt.rn.bf16.f32 %0, %1;" : "=h"(h) : "f"(f)); return h;
}
__device__ __forceinline__ u16 f2bf_hi(float f, float& fh) {
    u16 h; asm("cvt.rn.bf16.f32 %0, %1;" : "=h"(h) : "f"(f));
    fh = __uint_as_float(((u32)h) << 16); return h;
}
__device__ __forceinline__ u32 packbf(float lo, float hi) {
    u32 r; asm("cvt.rn.bf16x2.f32 %0, %1, %2;" : "=r"(r) : "f"(hi), "f"(lo)); return r;
}
__device__ __forceinline__ void mma_bf16(float* d, const u32* a, const u32* b) {
    asm volatile(
        "mma.sync.aligned.m16n8k16.row.col.f32.bf16.bf16.f32 "
        "{%0,%1,%2,%3},{%4,%5,%6,%7},{%8,%9},{%0,%1,%2,%3};"
        : "+f"(d[0]), "+f"(d[1]), "+f"(d[2]), "+f"(d[3])
        : "r"(a[0]), "r"(a[1]), "r"(a[2]), "r"(a[3]), "r"(b[0]), "r"(b[1]));
}
__device__ __forceinline__ void ldsm4(u32 addr, u32* r) {
    asm volatile("ldmatrix.sync.aligned.m8n8.x4.shared.b16 {%0,%1,%2,%3}, [%4];"
        : "=r"(r[0]), "=r"(r[1]), "=r"(r[2]), "=r"(r[3]) : "r"(addr));
}
__device__ __forceinline__ u32 smem_u32(const void* p) {
    u32 a;
    asm("{ .reg .u64 t; cvta.to.shared.u64 t, %1; cvt.u32.u64 %0, t; }" : "=r"(a) : "l"(p));
    return a;
}
__device__ __forceinline__ void cp16(u32 dst, const void* src) {
    asm volatile("cp.async.ca.shared.global [%0], [%1], 16;" :: "r"(dst), "l"(src));
}
__device__ __forceinline__ void cp_commit() {
    asm volatile("cp.async.commit_group;" ::: "memory");
}
__device__ __forceinline__ void cp_wait0() {
    asm volatile("cp.async.wait_group 0;" ::: "memory");
}

// Pairwise-fused K=64 product: A planes loaded ONCE feed two B operands.
//   accP += (Ah+Al)*B1h + Ah*B1l
//   accQ += (Ah+Al)*B2h + Ah*B2l
// Term groups alternate acc sets -> same-acc reuse distance >= 8 MMA issues.
__device__ __forceinline__ void mma_pair(float accP[2][2][4], float accQ[2][2][4],
                                         const u32* aH, const u32* aL,
                                         u32 b1H, u32 b1L, u32 b2H, u32 b2L) {
#pragma unroll
    for (int kk = 0; kk < 4; ++kk) {
        u32 ah[2][4], al[2][4], b1h[4], b1l[4], b2h[4], b2l[4];
        ldsm4(aH[0] + kk * 32, ah[0]);
        ldsm4(aH[1] + kk * 32, ah[1]);
        ldsm4(aL[0] + kk * 32, al[0]);
        ldsm4(aL[1] + kk * 32, al[1]);
        ldsm4(b1H + kk * 32, b1h);
        ldsm4(b1L + kk * 32, b1l);
        ldsm4(b2H + kk * 32, b2h);
        ldsm4(b2L + kk * 32, b2l);
#pragma unroll
        for (int mt = 0; mt < 2; ++mt)
#pragma unroll
            for (int nt = 0; nt < 2; ++nt)
                mma_bf16(accP[mt][nt], ah[mt], b1h + nt * 2);
#pragma unroll
        for (int mt = 0; mt < 2; ++mt)
#pragma unroll
            for (int nt = 0; nt < 2; ++nt)
                mma_bf16(accQ[mt][nt], ah[mt], b2h + nt * 2);
#pragma unroll
        for (int mt = 0; mt < 2; ++mt)
#pragma unroll
            for (int nt = 0; nt < 2; ++nt)
                mma_bf16(accP[mt][nt], ah[mt], b1l + nt * 2);
#pragma unroll
        for (int mt = 0; mt < 2; ++mt)
#pragma unroll
            for (int nt = 0; nt < 2; ++nt)
                mma_bf16(accQ[mt][nt], ah[mt], b2l + nt * 2);
#pragma unroll
        for (int mt = 0; mt < 2; ++mt)
#pragma unroll
            for (int nt = 0; nt < 2; ++nt)
                mma_bf16(accP[mt][nt], al[mt], b1h + nt * 2);
#pragma unroll
        for (int mt = 0; mt < 2; ++mt)
#pragma unroll
            for (int nt = 0; nt < 2; ++nt)
                mma_bf16(accQ[mt][nt], al[mt], b2h + nt * 2);
    }
}

// N=128 K=64 block (GEMM1), term-outer ordering
__device__ __forceinline__ void mma_blk128(float acc[2][4][4],
                                           const u32* aH, const u32* aL,
                                           const u32* bHp, const u32* bLp) {
#pragma unroll
    for (int kk = 0; kk < 4; ++kk) {
        u32 ah[2][4], al[2][4], b_h[2][4], b_l[2][4];
        ldsm4(aH[0] + kk * 32, ah[0]);
        ldsm4(aH[1] + kk * 32, ah[1]);
        ldsm4(aL[0] + kk * 32, al[0]);
        ldsm4(aL[1] + kk * 32, al[1]);
        ldsm4(bHp[0] + kk * 32, b_h[0]);
        ldsm4(bHp[1] + kk * 32, b_h[1]);
        ldsm4(bLp[0] + kk * 32, b_l[0]);
        ldsm4(bLp[1] + kk * 32, b_l[1]);
#pragma unroll
        for (int mt = 0; mt < 2; ++mt)
#pragma unroll
            for (int nt = 0; nt < 4; ++nt)
                mma_bf16(acc[mt][nt], ah[mt], &b_h[nt >> 1][(nt & 1) * 2]);
#pragma unroll
        for (int mt = 0; mt < 2; ++mt)
#pragma unroll
            for (int nt = 0; nt < 4; ++nt)
                mma_bf16(acc[mt][nt], ah[mt], &b_l[nt >> 1][(nt & 1) * 2]);
#pragma unroll
        for (int mt = 0; mt < 2; ++mt)
#pragma unroll
            for (int nt = 0; nt < 4; ++nt)
                mma_bf16(acc[mt][nt], al[mt], &b_h[nt >> 1][(nt & 1) * 2]);
    }
}

// ---------------------------------------------------------------------------
// Unitary builder (blocks 0..4) + MLP weight prep (block 5).
// ---------------------------------------------------------------------------
__global__ void build_all(const float* __restrict__ mzi,
                          const float* __restrict__ ophase,
                          const float* __restrict__ W1,
                          const float* __restrict__ W2) {
    const int l = blockIdx.x;
    const int t = threadIdx.x;

    if (l == NL) {
        for (int idx = t; idx < 8192; idx += TPB) {
            int m = idx >> 6, j = idx & 63;
            float v = W1[idx];
            float fh; u16 h = f2bf_hi(v, fh); u16 lo = f2bf(v - fh);
            g_Bw1[m * 72 + j] = h;
            g_Bw1[128 * 72 + m * 72 + j] = lo;
        }
        for (int idx = t; idx < 8192; idx += TPB) {
            int n = idx >> 7, m = idx & 127;
            float v = W2[idx];
            float fh; u16 h = f2bf_hi(v, fh); u16 lo = f2bf(v - fh);
            g_Bw2[n * 136 + m] = h;
            g_Bw2[64 * 136 + n * 136 + m] = lo;
        }
        return;
    }

    extern __shared__ char sm[];
    float4* strig = (float4*)sm;
    float2* sU    = (float2*)(sm + 32272);
    float*  sco   = (float*)(sm + 67088);
    float*  ssi   = (float*)(sm + 67344);

    for (int k = t; k < NMZI; k += TPB) {
        float th = mzi[l * (2 * NMZI) + 2 * k];
        float ph = mzi[l * (2 * NMZI) + 2 * k + 1];
        float st, ct, sp, cp;
        sincosf(th, &st, &ct);
        sincosf(ph, &sp, &cp);
        strig[k] = make_float4(ct, st, CHALF * cp, CHALF * sp);
    }
    if (t == 0) strig[NMZI] = make_float4(0.f, 0.f, 0.f, 0.f);
    if (t < 64) {
        float s, c; sincosf(ophase[l * NF + t], &s, &c);
        sco[t] = c; ssi[t] = s;
    }
    for (int idx = t; idx < 68 * NF; idx += TPB) {
        int r = idx >> 6, c = idx & 63;
        sU[idx] = make_float2((r == c && r < 64) ? 1.f : 0.f, 0.f);
    }
    __syncthreads();

    if (t < 64) {
        int k = 0;
        for (int i = 0; i < 63; ++i) {
            float2 ui = sU[i * NF + t];
            float2 uj = sU[(i + 1) * NF + t];
            float4 tr = strig[k];
            for (int j = i + 1; j < 64; ++j) {
                float4 trn = strig[k + 1];
                float2 ujn = sU[(j + 1) * NF + t];
                float cepx = tr.z * uj.x - tr.w * uj.y;
                float cepy = tr.z * uj.y + tr.w * uj.x;
                float dxC = fmaf(CHALF, ui.x, -cepx);
                float dyC = fmaf(CHALF, ui.y, -cepy);
                float2 nj;
                nj.x = tr.x * dxC - tr.y * dyC;
                nj.y = tr.y * dxC + tr.x * dyC;
                sU[j * NF + t] = nj;
                ui.x = fmaf(CHALF, ui.x, cepx);
                ui.y = fmaf(CHALF, ui.y, cepy);
                uj = ujn; tr = trn; ++k;
            }
            sU[i * NF + t] = ui;
        }
    }
    __syncthreads();

    u16* gb = g_Bu + l * 18432;
    for (int idx = t; idx < NF * NF; idx += TPB) {
        int c = idx >> 6, j = idx & 63;
        float co = sco[c], si = ssi[c];
        float2 v = sU[c * NF + j];
        float ur = co * v.x - si * v.y;
        float um = co * v.y + si * v.x;
        float fh;
        u16 urh = f2bf_hi(ur, fh); u16 url = f2bf(ur - fh);
        u16 uih = f2bf_hi(um, fh); u16 uil = f2bf(um - fh);
        int w = c * 72 + j;
        gb[w]         = urh;
        gb[4608 + w]  = uih;
        gb[9216 + w]  = url;
        gb[13824 + w] = uil;
    }
}

// ---------------------------------------------------------------------------
// Main fused kernel.
// ---------------------------------------------------------------------------
__global__ __launch_bounds__(TPB, 2)
void ficonn_main(const float* __restrict__ x,
                 const float* __restrict__ beta_param,
                 const float* __restrict__ det0,
                 const float* __restrict__ b1,
                 const float* __restrict__ b2,
                 const float* __restrict__ W3, const float* __restrict__ b3,
                 float* __restrict__ out)
{
    extern __shared__ char smem[];
    const u32 sb = smem_u32(smem);
    const int t = threadIdx.x;
    const int wid = t >> 5;
    const int lane = t & 31;
    const int g = lane >> 2;
    const int q = lane & 3;
    const long base = (long)blockIdx.x * TILE_R;

    float4* sPar = (float4*)(smem + OFF_PAR);
    float*  sB1  = (float*)(smem + OFF_B1);
    float*  sB2  = (float*)(smem + OFF_B2);
    float*  sH2  = (float*)(smem + OFF_H2);

    const int m0  = (wid >> 2) * 32;
    const int nb  = (wid & 3) * 16;
    const int n0  = (wid & 3) * 32;

    const int mi    = lane >> 3;
    const int arow  = (mi & 1) * 8 + (lane & 7);
    const int aseg  = (mi >> 1) * 4;
    const int brow8 = (lane & 7);
    const int bnt   = (lane >> 4);
    const int bseg  = ((lane >> 3) & 1) * 4;

    // A plane frags: frH(0) frL(1) fiH(2) fiL(3)
    u32 aFrH[2], aFrL[2], aFiH[2], aFiL[2];
#pragma unroll
    for (int mt = 0; mt < 2; ++mt) {
        u32 off = 4 * ((m0 + mt * 16 + arow) * AW + aseg);
        aFrH[mt] = sb + OFF_A + 0 * APL + off;
        aFrL[mt] = sb + OFF_A + 1 * APL + off;
        aFiH[mt] = sb + OFF_A + 2 * APL + off;
        aFiL[mt] = sb + OFF_A + 3 * APL + off;
    }
    // B frags: UrH(0) UiH(1) UrL(2) UiL(3)
    const u32 bOff = 4 * ((nb + bnt * 8 + brow8) * AW + bseg);
    const u32 bUrH = sb + OFF_B + 0 * APL + bOff;
    const u32 bUiH = sb + OFF_B + 1 * APL + bOff;
    const u32 bUrL = sb + OFF_B + 2 * APL + bOff;
    const u32 bUiL = sb + OFF_B + 3 * APL + bOff;
    // W1 frags (N=128, stride AW)
    u32 w1H[2], w1L[2];
#pragma unroll
    for (int ntp = 0; ntp < 2; ++ntp) {
        u32 off = 4 * ((n0 + (ntp * 2 + bnt) * 8 + brow8) * AW + bseg);
        w1H[ntp] = sb + OFF_B + off;
        w1L[ntp] = sb + OFF_B + 18432 + off;
    }

    u32* pA = (u32*)(smem + OFF_A);

    // ---- init ----
    {
        const uint4* src = (const uint4*)g_Bu;
#pragma unroll
        for (int i = 0; i < 9; ++i)
            cp16(sb + OFF_B + 16 * (t + i * TPB), src + t + i * TPB);
        cp_commit();

        const float4* xv = (const float4*)(x + base * NF);
        for (int idx = t; idx < TILE_R * (NF / 4); idx += TPB) {
            int r = idx >> 4, c4 = (idx & 15) * 4;
            float4 v = xv[idx];
            u32 w01 = packbf(v.x, v.y);
            u32 w23 = packbf(v.z, v.w);
            float l0 = v.x - __uint_as_float(w01 << 16);
            float l1 = v.y - __uint_as_float(w01 & 0xFFFF0000u);
            float l2 = v.z - __uint_as_float(w23 << 16);
            float l3 = v.w - __uint_as_float(w23 & 0xFFFF0000u);
            int w = r * AW + (c4 >> 1);
            *(uint2*)(pA + w) = make_uint2(w01, w23);
            *(uint2*)(pA + APL / 4 + w) = make_uint2(packbf(l0, l1), packbf(l2, l3));
        }
        {
            int ll = t >> 6, c = t & 63;
            if (ll < NL - 1) {
                float bp = beta_param[ll * NF + c];
                float beta = 1.f / (1.f + expf(-bp));
                float sgam = sqrtf(fmaxf(1.f - beta, 0.f)) * GAM;
                sPar[t] = make_float4(sgam, 0.0008f * beta, det0[ll * NF + c], 0.f);
            }
        }
        if (t < 128) sB1[t] = b1[t];
        else if (t < 192) sB2[t - 128] = b2[t - 128];
    }

    // ================= photonic layers =================
    for (int l = 0; l < NL; ++l) {
        cp_wait0();
        __syncthreads();   // A + B(l) ready

        float a1[2][2][4], a2[2][2][4], aI[2][2][4];
#pragma unroll
        for (int mt = 0; mt < 2; ++mt)
#pragma unroll
            for (int nt = 0; nt < 2; ++nt)
#pragma unroll
                for (int e = 0; e < 4; ++e) {
                    a1[mt][nt][e] = 0.f; a2[mt][nt][e] = 0.f; aI[mt][nt][e] = 0.f;
                }

        // pair A: fr -> (a1 += fr*Ur, aI += fr*Ui)
        mma_pair(a1, aI, aFrH, aFrL, bUrH, bUrL, bUiH, bUiL);
        // pair B: fi -> (a2 += fi*Ui, aI += fi*Ur)
        if (l > 0)
            mma_pair(a2, aI, aFiH, aFiL, bUiH, bUiL, bUrH, bUrL);
        __syncthreads();   // A + B reads done

        // stage next B (or W1) — overlaps epilogue
        {
            const uint4* src = (l < NL - 1)
                ? (const uint4*)(g_Bu + (l + 1) * 18432)
                : (const uint4*)g_Bw1;
#pragma unroll
            for (int i = 0; i < 9; ++i)
                cp16(sb + OFF_B + 16 * (t + i * TPB), src + t + i * TPB);
            cp_commit();
        }

        if (l < NL - 1) {
#pragma unroll
            for (int mt = 0; mt < 2; ++mt) {
#pragma unroll
                for (int nt = 0; nt < 2; ++nt) {
                    int c0 = nb + nt * 8 + q * 2;
                    float4 pr0 = sPar[l * 64 + c0];
                    float4 pr1 = sPar[l * 64 + c0 + 1];
#pragma unroll
                    for (int h = 0; h < 2; ++h) {
                        int row = m0 + mt * 16 + g + h * 8;
                        float ox[2], oy[2];
#pragma unroll
                        for (int e = 0; e < 2; ++e) {
                            float fx = a1[mt][nt][2 * h + e] - a2[mt][nt][2 * h + e];
                            float fy = aI[mt][nt][2 * h + e];
                            float4 pr = e ? pr1 : pr0;
                            float pw = fx * fx + fy * fy;
                            float det = fmaf(pr.y, pw, pr.z);
                            float s = pr.x * __fdividef(1.f, fmaf(det, det, GAM2));
                            ox[e] = s * fmaf(fy, det, fx * GAM);
                            oy[e] = s * fmaf(-fx, det, fy * GAM);
                        }
                        u32 frh = packbf(ox[0], ox[1]);
                        u32 frl = packbf(ox[0] - __uint_as_float(frh << 16),
                                         ox[1] - __uint_as_float(frh & 0xFFFF0000u));
                        u32 fih = packbf(oy[0], oy[1]);
                        u32 fil = packbf(oy[0] - __uint_as_float(fih << 16),
                                         oy[1] - __uint_as_float(fih & 0xFFFF0000u));
                        int w = row * AW + (c0 >> 1);
                        pA[w]               = frh;
                        pA[APL / 4 + w]     = frl;
                        pA[2 * APL / 4 + w] = fih;
                        pA[3 * APL / 4 + w] = fil;
                    }
                }
            }
        } else {
            // |field|^2 -> P planes (fr slots)
#pragma unroll
            for (int mt = 0; mt < 2; ++mt) {
#pragma unroll
                for (int nt = 0; nt < 2; ++nt) {
                    int c0 = nb + nt * 8 + q * 2;
#pragma unroll
                    for (int h = 0; h < 2; ++h) {
                        int row = m0 + mt * 16 + g + h * 8;
                        float fx0 = a1[mt][nt][2 * h]     - a2[mt][nt][2 * h];
                        float fx1 = a1[mt][nt][2 * h + 1] - a2[mt][nt][2 * h + 1];
                        float fy0 = aI[mt][nt][2 * h], fy1 = aI[mt][nt][2 * h + 1];
                        float pw0 = fx0 * fx0 + fy0 * fy0;
                        float pw1 = fx1 * fx1 + fy1 * fy1;
                        u32 ph = packbf(pw0, pw1);
                        u32 pl = packbf(pw0 - __uint_as_float(ph << 16),
                                        pw1 - __uint_as_float(ph & 0xFFFF0000u));
                        int w = row * AW + (c0 >> 1);
                        pA[w]           = ph;
                        pA[APL / 4 + w] = pl;
                    }
                }
            }
        }
    }
    cp_wait0();
    __syncthreads();   // P + W1 ready

    // ================= GEMM1: M=64 N=128 K=64 =================
    {
        float acc[2][4][4];
#pragma unroll
        for (int mt = 0; mt < 2; ++mt)
#pragma unroll
            for (int nt = 0; nt < 4; ++nt)
#pragma unroll
                for (int e = 0; e < 4; ++e) acc[mt][nt][e] = 0.f;

        mma_blk128(acc, aFrH, aFrL, w1H, w1L);
        __syncthreads();

        // stage W2 (34816 B = 2176 uint4)
        {
            const uint4* src = (const uint4*)g_Bw2;
            for (int i = t; i < 2176; i += TPB) cp16(sb + OFF_B + 16 * i, src + i);
            cp_commit();
        }
        // epilogue: relu+bias -> h1 planes (K=128 layout, stride HW)
#pragma unroll
        for (int mt = 0; mt < 2; ++mt) {
#pragma unroll
            for (int nt = 0; nt < 4; ++nt) {
                int col = n0 + nt * 8 + q * 2;
                float bb0 = sB1[col], bb1 = sB1[col + 1];
#pragma unroll
                for (int h = 0; h < 2; ++h) {
                    int row = m0 + mt * 16 + g + h * 8;
                    float v0 = fmaxf(acc[mt][nt][2 * h] + bb0, 0.f);
                    float v1 = fmaxf(acc[mt][nt][2 * h + 1] + bb1, 0.f);
                    u32 whi = packbf(v0, v1);
                    float l0 = v0 - __uint_as_float(whi << 16);
                    float l1 = v1 - __uint_as_float(whi & 0xFFFF0000u);
                    int w = row * HW + (col >> 1);
                    pA[w] = whi;
                    pA[17408 / 4 + w] = packbf(l0, l1);
                }
            }
        }
    }
    cp_wait0();
    __syncthreads();

    // ================= GEMM2: M=64 N=64 K=128 =================
    {
        const int mb  = (wid >> 1) * 16;
        const int nb2 = (wid & 1) * 32;

        u32 aA2h = sb + OFF_A + 4 * ((mb + arow) * HW + aseg);
        u32 aA2l = aA2h + 17408;
        u32 b2H[2], b2L[2];
#pragma unroll
        for (int ntp = 0; ntp < 2; ++ntp) {
            u32 off = 4 * ((nb2 + (ntp * 2 + bnt) * 8 + brow8) * HW + bseg);
            b2H[ntp] = sb + OFF_B + off;
            b2L[ntp] = sb + OFF_B + 17408 + off;
        }

        float acc[4][4];
#pragma unroll
        for (int nt = 0; nt < 4; ++nt)
#pragma unroll
            for (int e = 0; e < 4; ++e) acc[nt][e] = 0.f;

#pragma unroll
        for (int kk = 0; kk < 8; ++kk) {
            u32 ah[4], al[4], b_h[2][4], b_l[2][4];
            ldsm4(aA2h + kk * 32, ah);
            ldsm4(aA2l + kk * 32, al);
            ldsm4(b2H[0] + kk * 32, b_h[0]);
            ldsm4(b2H[1] + kk * 32, b_h[1]);
            ldsm4(b2L[0] + kk * 32, b_l[0]);
            ldsm4(b2L[1] + kk * 32, b_l[1]);
#pragma unroll
            for (int nt = 0; nt < 4; ++nt)
                mma_bf16(acc[nt], ah, &b_h[nt >> 1][(nt & 1) * 2]);
#pragma unroll
            for (int nt = 0; nt < 4; ++nt)
                mma_bf16(acc[nt], ah, &b_l[nt >> 1][(nt & 1) * 2]);
#pragma unroll
            for (int nt = 0; nt < 4; ++nt)
                mma_bf16(acc[nt], al, &b_h[nt >> 1][(nt & 1) * 2]);
        }
        __syncthreads();   // h1/W2 reads done

        {
            float* sW3 = (float*)(smem + OFF_W3);
            for (int i = t; i < NCLS * 64; i += TPB) sW3[i] = W3[i];
        }
#pragma unroll
        for (int nt = 0; nt < 4; ++nt) {
            int col = nb2 + nt * 8 + q * 2;
            float bb0 = sB2[col], bb1 = sB2[col + 1];
#pragma unroll
            for (int h = 0; h < 2; ++h) {
                int row = mb + g + h * 8;
                sH2[row * 68 + col]     = fmaxf(acc[nt][2 * h] + bb0, 0.f);
                sH2[row * 68 + col + 1] = fmaxf(acc[nt][2 * h + 1] + bb1, 0.f);
            }
        }
    }
    __syncthreads();

    // ================= GEMM3 (scalar) =================
    {
        const float* sW3 = (const float*)(smem + OFF_W3);
        const int rr = t >> 2;
        const int ch = (t & 3) * 3;
        float acc[3] = {0.f, 0.f, 0.f};
#pragma unroll 4
        for (int j = 0; j < 64; ++j) {
            float h = sH2[rr * 68 + j];
#pragma unroll
            for (int c = 0; c < 3; ++c)
                acc[c] = fmaf(h, sW3[(ch + c) * 64 + j], acc[c]);
        }
#pragma unroll
        for (int c = 0; c < 3; ++c)
            out[(base + rr) * NCLS + ch + c] = acc[c] + b3[ch + c];
    }
}

// ---------------------------------------------------------------------------
extern "C" void kernel_launch(void* const* d_in, const int* in_sizes, int n_in,
                              void* d_out, int out_size) {
    const float* x     = (const float*)d_in[0];
    const float* mzi   = (const float*)d_in[1];
    const float* oph   = (const float*)d_in[2];
    const float* betap = (const float*)d_in[3];
    const float* det0  = (const float*)d_in[4];
    const float* W1    = (const float*)d_in[5];
    const float* b1    = (const float*)d_in[6];
    const float* W2    = (const float*)d_in[7];
    const float* b2    = (const float*)d_in[8];
    const float* W3    = (const float*)d_in[9];
    const float* b3    = (const float*)d_in[10];
    float* out = (float*)d_out;

    const int rows = in_sizes[0] / NF;
    const int grid = rows / TILE_R;

    cudaFuncSetAttribute(build_all, cudaFuncAttributeMaxDynamicSharedMemorySize, 67712);
    cudaFuncSetAttribute(ficonn_main, cudaFuncAttributeMaxDynamicSharedMemorySize, SMEM_TOTAL);

    build_all<<<NL + 1, TPB, 67712>>>(mzi, oph, W1, W2);
    ficonn_main<<<grid, TPB, SMEM_TOTAL>>>(x, betap, det0, b1, b2, W3, b3, out);
}